// round 7
// baseline (speedup 1.0000x reference)
#include <cuda_runtime.h>
#include <cuda_bf16.h>
#include <math.h>
#include <stdint.h>

#define BB 32
#define TT 2048
#define HH 512

#define MT  128                 // t-rows per CTA
#define KC  64                  // K-chunk
#define NOCH 4                  // N chunks of 128
#define NKC (HH / KC)           // 8

// ---------------- scratch (device globals; no allocation allowed) ----------
__device__ float g_q[BB * HH];
__device__ float g_p[BB * TT];
__device__ float g_ctx[BB * HH];
__device__ float g_sum[BB];
__device__ __nv_bfloat16 g_bwhi[HH * HH];
__device__ __nv_bfloat16 g_bwlo[HH * HH];
__device__ __nv_bfloat16 g_vhi[BB * TT * HH];   // 64MB
__device__ __nv_bfloat16 g_vlo[BB * TT * HH];   // 64MB

// ---------------- SMEM layout (byte offsets from 1024-aligned base) --------
#define TILE_SZ  16384
#define BUF_SZ   65536
#define OFF_QB   131072
#define OFF_W0   133120
#define OFF_W1   135168
#define OFF_W2   137216
#define OFF_SW   139264
#define OFF_LA   141312    // 130 floats
#define OFF_SC   141888    // 128 floats
#define SMEM_END 142400
#define SMEM_REQ (SMEM_END + 1024)

// ---------------- helpers ---------------------------------------------------
__device__ __forceinline__ uint32_t smem_u32(const void* p) {
    uint32_t a;
    asm("{ .reg .u64 t; cvta.to.shared.u64 t, %1; cvt.u32.u64 %0, t; }"
        : "=r"(a) : "l"(p));
    return a;
}
__device__ __forceinline__ uint64_t gaddr(const void* p) {
    uint64_t a;
    asm("cvta.to.global.u64 %0, %1;" : "=l"(a) : "l"(p));
    return a;
}
__device__ __forceinline__ void cpa16(uint32_t d, uint64_t s) {
    asm volatile("cp.async.cg.shared.global [%0], [%1], 16;"
                 :: "r"(d), "l"(s) : "memory");
}
#define CP_COMMIT() asm volatile("cp.async.commit_group;" ::: "memory")
#define CP_WAIT0()  asm volatile("cp.async.wait_group 0;" ::: "memory")
#define CP_WAIT1()  asm volatile("cp.async.wait_group 1;" ::: "memory")

__device__ __forceinline__ void ldsm4(uint32_t* r, uint32_t a) {
    asm volatile("ldmatrix.sync.aligned.m8n8.x4.shared.b16 {%0,%1,%2,%3}, [%4];"
                 : "=r"(r[0]), "=r"(r[1]), "=r"(r[2]), "=r"(r[3]) : "r"(a));
}
__device__ __forceinline__ void mma16816(float* d, const uint32_t* a,
                                         const uint32_t* b) {
    asm volatile(
        "mma.sync.aligned.m16n8k16.row.col.f32.bf16.bf16.f32 "
        "{%0,%1,%2,%3},{%4,%5,%6,%7},{%8,%9},{%0,%1,%2,%3};"
        : "+f"(d[0]), "+f"(d[1]), "+f"(d[2]), "+f"(d[3])
        : "r"(a[0]), "r"(a[1]), "r"(a[2]), "r"(a[3]), "r"(b[0]), "r"(b[1]));
}
__device__ __forceinline__ float ftanh(float x) {
    float e = __expf(2.f * x);
    return 1.f - __fdividef(2.f, e + 1.f);
}
__device__ __forceinline__ uint32_t pkbf(float a, float b) {
    return ((uint32_t)__bfloat16_as_ushort(__float2bfloat16(b)) << 16)
         |  (uint32_t)__bfloat16_as_ushort(__float2bfloat16(a));
}

// ---------------- init: zero scratch + split v_w ----------------------------
__global__ void k_init(const float* __restrict__ v_w) {
    int i = blockIdx.x * 256 + threadIdx.x;
    if (i < BB * HH) g_ctx[i] = 0.f;
    if (i < BB)      g_sum[i] = 0.f;
    if (i < HH * HH) {
        float x = v_w[i];
        __nv_bfloat16 h = __float2bfloat16(x);
        g_bwhi[i] = h;
        g_bwlo[i] = __float2bfloat16(x - __bfloat162float(h));
    }
}

__global__ void k_convv(const float* __restrict__ value) {
    long i4 = (long)blockIdx.x * 256 + threadIdx.x;       // 4 elems each
    float4 v = *((const float4*)value + i4);
    float hx = __bfloat162float(__float2bfloat16(v.x));
    float hy = __bfloat162float(__float2bfloat16(v.y));
    float hz = __bfloat162float(__float2bfloat16(v.z));
    float hw = __bfloat162float(__float2bfloat16(v.w));
    ((uint2*)g_vhi)[i4] = make_uint2(pkbf(v.x, v.y), pkbf(v.z, v.w));
    ((uint2*)g_vlo)[i4] = make_uint2(pkbf(v.x - hx, v.y - hy),
                                     pkbf(v.z - hz, v.w - hw));
}

// q[b,o]: one block per o; warp w covers b in [4w, 4w+4)
__global__ void __launch_bounds__(256)
k_qproj(const float* __restrict__ query, const float* __restrict__ q_w) {
    int o = blockIdx.x, lane = threadIdx.x & 31, warp = threadIdx.x >> 5;
    const float* wrow = q_w + o * HH;
    float acc0 = 0.f, acc1 = 0.f, acc2 = 0.f, acc3 = 0.f;
    int b0 = warp * 4;
    for (int k = lane; k < HH; k += 32) {
        float w = __ldg(wrow + k);
        acc0 += w * __ldg(query + (b0 + 0) * HH + k);
        acc1 += w * __ldg(query + (b0 + 1) * HH + k);
        acc2 += w * __ldg(query + (b0 + 2) * HH + k);
        acc3 += w * __ldg(query + (b0 + 3) * HH + k);
    }
    #pragma unroll
    for (int off = 16; off; off >>= 1) {
        acc0 += __shfl_xor_sync(0xffffffffu, acc0, off);
        acc1 += __shfl_xor_sync(0xffffffffu, acc1, off);
        acc2 += __shfl_xor_sync(0xffffffffu, acc2, off);
        acc3 += __shfl_xor_sync(0xffffffffu, acc3, off);
    }
    if (lane == 0) {
        g_q[(b0 + 0) * HH + o] = acc0;
        g_q[(b0 + 1) * HH + o] = acc1;
        g_q[(b0 + 2) * HH + o] = acc2;
        g_q[(b0 + 3) * HH + o] = acc3;
    }
}

// ---------------- main HMMA kernel (512 threads, 4x4 warp grid) -------------
__global__ void __launch_bounds__(512, 1)
k_main(const float* __restrict__ la,
       const float* __restrict__ conv_w, const float* __restrict__ conv_b,
       const float* __restrict__ s_w,    const float* __restrict__ s_b,
       const float* __restrict__ bias)
{
    extern __shared__ char smraw[];
    uint32_t raw = smem_u32(smraw);
    uint32_t sb  = (raw + 1023) & ~1023u;
    char* base   = smraw + (sb - raw);

    int tid = threadIdx.x, L = tid & 31, wid = tid >> 5;
    int warp_m = wid >> 2, warp_n = wid & 3;      // 4 x 4
    int b = blockIdx.y, t0 = blockIdx.x * MT;

    uint64_t vhiG = gaddr(g_vhi) + (uint64_t)(((long)b * TT + t0) * HH) * 2;
    uint64_t vloG = gaddr(g_vlo) + (uint64_t)(((long)b * TT + t0) * HH) * 2;
    uint64_t bwhG = gaddr(g_bwhi);
    uint64_t bwlG = gaddr(g_bwlo);

    auto issue_chunk = [&](int pc) {
        int och = pc >> 3, kc = pc & 7;
        int kt = kc * KC, o0 = och * 128;
        uint32_t tb = sb + (uint32_t)(pc & 1) * BUF_SZ;
        #pragma unroll
        for (int i = 0; i < 2; i++) {
            int id  = tid + i * 512;          // 1024 16B-chunks per tile
            int row = id >> 3, c8 = id & 7;
            uint32_t so = (uint32_t)(row * 128 + ((c8 * 16) ^ ((row & 7) << 4)));
            uint64_t ga = (uint64_t)((long)row * HH + kt + c8 * 8) * 2;
            uint64_t gb = (uint64_t)((long)(o0 + row) * HH + kt + c8 * 8) * 2;
            cpa16(tb + 0 * TILE_SZ + so, vhiG + ga);
            cpa16(tb + 1 * TILE_SZ + so, vloG + ga);
            cpa16(tb + 2 * TILE_SZ + so, bwhG + gb);
            cpa16(tb + 3 * TILE_SZ + so, bwlG + gb);
        }
    };

    issue_chunk(0);
    CP_COMMIT();

    float* qbF = (float*)(base + OFF_QB);
    float* w0F = (float*)(base + OFF_W0);
    float* w1F = (float*)(base + OFF_W1);
    float* w2F = (float*)(base + OFF_W2);
    float* swF = (float*)(base + OFF_SW);
    float* laF = (float*)(base + OFF_LA);
    float* scS = (float*)(base + OFF_SC);
    for (int i = tid; i < HH; i += 512) {
        qbF[i] = g_q[b * HH + i] + bias[i] + conv_b[i];
        w0F[i] = conv_w[i * 3 + 0];
        w1F[i] = conv_w[i * 3 + 1];
        w2F[i] = conv_w[i * 3 + 2];
        swF[i] = s_w[i];
    }
    for (int i = tid; i < MT + 2; i += 512) {
        int gt = t0 - 1 + i;
        laF[i] = (gt >= 0 && gt < TT) ? la[b * TT + gt] : 0.f;
    }
    if (tid < 128) scS[tid] = 0.f;

    // each warp: 32 rows (2 x m16), 32 cols (4 x n8)
    uint32_t aRow  = (uint32_t)(warp_m * 32 + (L & 15)) * 128;
    uint32_t bRow  = (uint32_t)(warp_n * 32 + (L & 7) + ((L >> 4) << 3)) * 128;
    uint32_t amask = (uint32_t)(L & 7) << 4;
    uint32_t aColK[4], bColK[4];
    #pragma unroll
    for (int kk = 0; kk < 4; kk++) {
        aColK[kk] = (uint32_t)(kk * 32 + ((L >> 4) << 4)) ^ amask;
        bColK[kk] = (uint32_t)(kk * 32 + (((L >> 3) & 1) << 4)) ^ amask;
    }

    float scp[2][2];
    scp[0][0] = scp[0][1] = scp[1][0] = scp[1][1] = 0.f;

    int pc = 0;
    for (int och = 0; och < NOCH; och++) {
        float acc[2][4][4];
        #pragma unroll
        for (int mi = 0; mi < 2; mi++)
            #pragma unroll
            for (int ni = 0; ni < 4; ni++)
                #pragma unroll
                for (int q = 0; q < 4; q++) acc[mi][ni][q] = 0.f;

        for (int kc = 0; kc < NKC; kc++, pc++) {
            bool has_next = (pc + 1 < NOCH * NKC);
            if (has_next) { issue_chunk(pc + 1); CP_COMMIT(); CP_WAIT1(); }
            else          { CP_WAIT0(); }
            __syncthreads();

            uint32_t tb = sb + (uint32_t)(pc & 1) * BUF_SZ;
            uint32_t aH = tb + 0 * TILE_SZ + aRow;
            uint32_t aL = tb + 1 * TILE_SZ + aRow;
            uint32_t bH = tb + 2 * TILE_SZ + bRow;
            uint32_t bL = tb + 3 * TILE_SZ + bRow;

            #pragma unroll
            for (int kk = 0; kk < 4; kk++) {
                uint32_t ah[2][4], al[2][4], bh[4][2], bl[4][2];
                #pragma unroll
                for (int mi = 0; mi < 2; mi++) {
                    ldsm4(ah[mi], aH + (uint32_t)(mi * 2048) + aColK[kk]);
                    ldsm4(al[mi], aL + (uint32_t)(mi * 2048) + aColK[kk]);
                }
                #pragma unroll
                for (int n2 = 0; n2 < 2; n2++) {
                    uint32_t rh[4], rl[4];
                    ldsm4(rh, bH + (uint32_t)(n2 * 2048) + bColK[kk]);
                    ldsm4(rl, bL + (uint32_t)(n2 * 2048) + bColK[kk]);
                    bh[2*n2][0] = rh[0]; bh[2*n2][1] = rh[1];
                    bh[2*n2+1][0] = rh[2]; bh[2*n2+1][1] = rh[3];
                    bl[2*n2][0] = rl[0]; bl[2*n2][1] = rl[1];
                    bl[2*n2+1][0] = rl[2]; bl[2*n2+1][1] = rl[3];
                }
                #pragma unroll
                for (int mi = 0; mi < 2; mi++)
                    #pragma unroll
                    for (int ni = 0; ni < 4; ni++) {
                        mma16816(acc[mi][ni], ah[mi], bh[ni]);
                        mma16816(acc[mi][ni], ah[mi], bl[ni]);
                        mma16816(acc[mi][ni], al[mi], bh[ni]);
                    }
            }
            __syncthreads();
        }

        int o0 = och * 128;
        #pragma unroll
        for (int mi = 0; mi < 2; mi++) {
            int r0 = warp_m * 32 + mi * 16 + (L >> 2);
            float la0 = laF[r0],     la1 = laF[r0 + 1], la2 = laF[r0 + 2];
            float lb0 = laF[r0 + 8], lb1 = laF[r0 + 9], lb2 = laF[r0 + 10];
            #pragma unroll
            for (int ni = 0; ni < 4; ni++) {
                int c0 = o0 + warp_n * 32 + ni * 8 + (L & 3) * 2;
                float2 qb = *(const float2*)(qbF + c0);
                float2 w0 = *(const float2*)(w0F + c0);
                float2 w1 = *(const float2*)(w1F + c0);
                float2 w2 = *(const float2*)(w2F + c0);
                float2 sw = *(const float2*)(swF + c0);
                float cva0 = w0.x * la0 + w1.x * la1 + w2.x * la2 + qb.x;
                float cva1 = w0.y * la0 + w1.y * la1 + w2.y * la2 + qb.y;
                float cvb0 = w0.x * lb0 + w1.x * lb1 + w2.x * lb2 + qb.x;
                float cvb1 = w0.y * lb0 + w1.y * lb1 + w2.y * lb2 + qb.y;
                scp[mi][0] += sw.x * ftanh(acc[mi][ni][0] + cva0)
                            + sw.y * ftanh(acc[mi][ni][1] + cva1);
                scp[mi][1] += sw.x * ftanh(acc[mi][ni][2] + cvb0)
                            + sw.y * ftanh(acc[mi][ni][3] + cvb1);
            }
        }
    }

    #pragma unroll
    for (int mi = 0; mi < 2; mi++)
        #pragma unroll
        for (int h = 0; h < 2; h++) {
            float v = scp[mi][h];
            v += __shfl_xor_sync(0xffffffffu, v, 1);
            v += __shfl_xor_sync(0xffffffffu, v, 2);
            if ((L & 3) == 0) {
                int r = warp_m * 32 + mi * 16 + (L >> 2) + h * 8;
                atomicAdd(&scS[r], v);
            }
        }
    __syncthreads();

    if (tid < 128) {
        float s = scS[tid];
        float p = __fdividef(1.f, 1.f + __expf(-(s + s_b[0])));
        g_p[b * TT + t0 + tid] = p;
        #pragma unroll
        for (int off = 16; off; off >>= 1)
            p += __shfl_xor_sync(0xffffffffu, p, off);
        if ((tid & 31) == 0) atomicAdd(&g_sum[b], p);
    }
}

// ---------------- context: g_ctx[b,h] += sum_t p[b,t]*value[b,t,h] ----------
__global__ void __launch_bounds__(256)
k_ctx(const float* __restrict__ value) {
    int b = blockIdx.x, ts = blockIdx.y;
    int h2 = threadIdx.x;                       // float2 column index (0..255)
    const float2* vb = (const float2*)value + ((long)b * TT + ts * 256) * 256 + h2;
    const float* pb  = g_p + b * TT + ts * 256;
    float2 a0 = {0.f, 0.f}, a1 = {0.f, 0.f}, a2 = {0.f, 0.f}, a3 = {0.f, 0.f};
    #pragma unroll 4
    for (int t = 0; t < 256; t += 4) {
        float p0 = pb[t], p1 = pb[t + 1], p2 = pb[t + 2], p3 = pb[t + 3];
        float2 v0 = vb[(long)(t + 0) * 256];
        float2 v1 = vb[(long)(t + 1) * 256];
        float2 v2 = vb[(long)(t + 2) * 256];
        float2 v3 = vb[(long)(t + 3) * 256];
        a0.x += p0 * v0.x; a0.y += p0 * v0.y;
        a1.x += p1 * v1.x; a1.y += p1 * v1.y;
        a2.x += p2 * v2.x; a2.y += p2 * v2.y;
        a3.x += p3 * v3.x; a3.y += p3 * v3.y;
    }
    float rx = (a0.x + a1.x) + (a2.x + a3.x);
    float ry = (a0.y + a1.y) + (a2.y + a3.y);
    atomicAdd(&g_ctx[b * HH + 2 * h2 + 0], rx);
    atomicAdd(&g_ctx[b * HH + 2 * h2 + 1], ry);
}

__global__ void k_fin(float* __restrict__ out) {
    int i = blockIdx.x * 256 + threadIdx.x;
    if (i < BB * HH) out[i] = g_ctx[i] / g_sum[i / HH];
    if (i < BB * TT) out[BB * HH + i] = g_p[i] / g_sum[i / TT];
}

// ---------------------------------------------------------------------------
extern "C" void kernel_launch(void* const* d_in, const int* in_sizes, int n_in,
                              void* d_out, int out_size) {
    const float* query  = (const float*)d_in[0];
    const float* value  = (const float*)d_in[1];
    const float* la     = (const float*)d_in[2];
    const float* conv_w = (const float*)d_in[3];
    const float* conv_b = (const float*)d_in[4];
    const float* q_w    = (const float*)d_in[5];
    const float* v_w    = (const float*)d_in[6];
    const float* s_w    = (const float*)d_in[7];
    const float* s_b    = (const float*)d_in[8];
    const float* bias   = (const float*)d_in[9];
    float* out = (float*)d_out;

    cudaFuncSetAttribute(k_main, cudaFuncAttributeMaxDynamicSharedMemorySize,
                         SMEM_REQ);

    k_init<<<(HH * HH + 255) / 256, 256>>>(v_w);
    k_convv<<<(BB * TT * HH / 4 + 255) / 256, 256>>>(value);
    k_qproj<<<HH, 256>>>(query, q_w);
    k_main<<<dim3(TT / MT, BB), 512, SMEM_REQ>>>(la, conv_w, conv_b,
                                                 s_w, s_b, bias);
    k_ctx<<<dim3(BB, 8), 256>>>(value);
    k_fin<<<(BB * TT + 255) / 256, 256>>>(out);
}

// round 8
// speedup vs baseline: 1.1421x; 1.1421x over previous
#include <cuda_runtime.h>
#include <cuda_bf16.h>
#include <math.h>
#include <stdint.h>

#define BB 32
#define TT 2048
#define HH 512

#define MT  64                  // t-rows per CTA
#define KC  64                  // K-chunk
#define NOCH 4                  // N chunks of 128
#define NKC (HH / KC)           // 8

// ---------------- scratch (device globals; no allocation allowed) ----------
__device__ float g_q[BB * HH];
__device__ float g_p[BB * TT];
__device__ float g_ctx[BB * HH];
__device__ float g_sum[BB];
__device__ __nv_bfloat16 g_bwhi[HH * HH];
__device__ __nv_bfloat16 g_bwlo[HH * HH];
__device__ __nv_bfloat16 g_vhi[BB * TT * HH];   // 64MB
__device__ __nv_bfloat16 g_vlo[BB * TT * HH];   // 64MB

// ---------------- SMEM layout (byte offsets from 1024-aligned base) --------
// buffer: [AH 8K][AL 8K][BH 16K][BL 16K] = 48K, 2 buffers
#define OFF_AH   0
#define OFF_AL   8192
#define OFF_BH   16384
#define OFF_BL   32768
#define BUF_SZ   49152
#define OFF_QB   98304
#define OFF_W0   100352
#define OFF_W1   102400
#define OFF_W2   104448
#define OFF_SW   106496
#define OFF_LA   108544    // 66 floats
#define OFF_SC   109056    // 64 floats
#define SMEM_END 109568
#define SMEM_REQ (SMEM_END + 1024)   // 110592; x2 CTAs = 221184 <= 227KB

// ---------------- helpers ---------------------------------------------------
__device__ __forceinline__ uint32_t smem_u32(const void* p) {
    uint32_t a;
    asm("{ .reg .u64 t; cvta.to.shared.u64 t, %1; cvt.u32.u64 %0, t; }"
        : "=r"(a) : "l"(p));
    return a;
}
__device__ __forceinline__ uint64_t gaddr(const void* p) {
    uint64_t a;
    asm("cvta.to.global.u64 %0, %1;" : "=l"(a) : "l"(p));
    return a;
}
__device__ __forceinline__ void cpa16(uint32_t d, uint64_t s) {
    asm volatile("cp.async.cg.shared.global [%0], [%1], 16;"
                 :: "r"(d), "l"(s) : "memory");
}
#define CP_COMMIT() asm volatile("cp.async.commit_group;" ::: "memory")
#define CP_WAIT0()  asm volatile("cp.async.wait_group 0;" ::: "memory")
#define CP_WAIT1()  asm volatile("cp.async.wait_group 1;" ::: "memory")

__device__ __forceinline__ void ldsm4(uint32_t* r, uint32_t a) {
    asm volatile("ldmatrix.sync.aligned.m8n8.x4.shared.b16 {%0,%1,%2,%3}, [%4];"
                 : "=r"(r[0]), "=r"(r[1]), "=r"(r[2]), "=r"(r[3]) : "r"(a));
}
__device__ __forceinline__ void mma16816(float* d, const uint32_t* a,
                                         const uint32_t* b) {
    asm volatile(
        "mma.sync.aligned.m16n8k16.row.col.f32.bf16.bf16.f32 "
        "{%0,%1,%2,%3},{%4,%5,%6,%7},{%8,%9},{%0,%1,%2,%3};"
        : "+f"(d[0]), "+f"(d[1]), "+f"(d[2]), "+f"(d[3])
        : "r"(a[0]), "r"(a[1]), "r"(a[2]), "r"(a[3]), "r"(b[0]), "r"(b[1]));
}
__device__ __forceinline__ float ftanh(float x) {
    float e = __expf(2.f * x);
    return 1.f - __fdividef(2.f, e + 1.f);
}
__device__ __forceinline__ uint32_t pkbf(float a, float b) {
    return ((uint32_t)__bfloat16_as_ushort(__float2bfloat16(b)) << 16)
         |  (uint32_t)__bfloat16_as_ushort(__float2bfloat16(a));
}

// ---------------- init: zero scratch + split v_w ----------------------------
__global__ void k_init(const float* __restrict__ v_w) {
    int i = blockIdx.x * 256 + threadIdx.x;
    if (i < BB * HH) g_ctx[i] = 0.f;
    if (i < BB)      g_sum[i] = 0.f;
    if (i < HH * HH) {
        float x = v_w[i];
        __nv_bfloat16 h = __float2bfloat16(x);
        g_bwhi[i] = h;
        g_bwlo[i] = __float2bfloat16(x - __bfloat162float(h));
    }
}

__global__ void k_convv(const float* __restrict__ value) {
    long i4 = (long)blockIdx.x * 256 + threadIdx.x;       // 4 elems each
    float4 v = *((const float4*)value + i4);
    float hx = __bfloat162float(__float2bfloat16(v.x));
    float hy = __bfloat162float(__float2bfloat16(v.y));
    float hz = __bfloat162float(__float2bfloat16(v.z));
    float hw = __bfloat162float(__float2bfloat16(v.w));
    ((uint2*)g_vhi)[i4] = make_uint2(pkbf(v.x, v.y), pkbf(v.z, v.w));
    ((uint2*)g_vlo)[i4] = make_uint2(pkbf(v.x - hx, v.y - hy),
                                     pkbf(v.z - hz, v.w - hw));
}

// q[b,o]: one block per o; warp w covers b in [4w, 4w+4)
__global__ void __launch_bounds__(256)
k_qproj(const float* __restrict__ query, const float* __restrict__ q_w) {
    int o = blockIdx.x, lane = threadIdx.x & 31, warp = threadIdx.x >> 5;
    const float* wrow = q_w + o * HH;
    float acc0 = 0.f, acc1 = 0.f, acc2 = 0.f, acc3 = 0.f;
    int b0 = warp * 4;
    for (int k = lane; k < HH; k += 32) {
        float w = __ldg(wrow + k);
        acc0 += w * __ldg(query + (b0 + 0) * HH + k);
        acc1 += w * __ldg(query + (b0 + 1) * HH + k);
        acc2 += w * __ldg(query + (b0 + 2) * HH + k);
        acc3 += w * __ldg(query + (b0 + 3) * HH + k);
    }
    #pragma unroll
    for (int off = 16; off; off >>= 1) {
        acc0 += __shfl_xor_sync(0xffffffffu, acc0, off);
        acc1 += __shfl_xor_sync(0xffffffffu, acc1, off);
        acc2 += __shfl_xor_sync(0xffffffffu, acc2, off);
        acc3 += __shfl_xor_sync(0xffffffffu, acc3, off);
    }
    if (lane == 0) {
        g_q[(b0 + 0) * HH + o] = acc0;
        g_q[(b0 + 1) * HH + o] = acc1;
        g_q[(b0 + 2) * HH + o] = acc2;
        g_q[(b0 + 3) * HH + o] = acc3;
    }
}

// ---------------- main HMMA kernel (256 threads, 2x4 warp grid, 2 CTA/SM) ---
__global__ void __launch_bounds__(256, 2)
k_main(const float* __restrict__ la,
       const float* __restrict__ conv_w, const float* __restrict__ conv_b,
       const float* __restrict__ s_w,    const float* __restrict__ s_b,
       const float* __restrict__ bias)
{
    extern __shared__ char smraw[];
    uint32_t raw = smem_u32(smraw);
    uint32_t sb  = (raw + 1023) & ~1023u;
    char* base   = smraw + (sb - raw);

    int tid = threadIdx.x, L = tid & 31, wid = tid >> 5;
    int warp_m = wid >> 2, warp_n = wid & 3;      // 2 x 4
    int b = blockIdx.y, t0 = blockIdx.x * MT;

    uint64_t vhiG = gaddr(g_vhi) + (uint64_t)(((long)b * TT + t0) * HH) * 2;
    uint64_t vloG = gaddr(g_vlo) + (uint64_t)(((long)b * TT + t0) * HH) * 2;
    uint64_t bwhG = gaddr(g_bwhi);
    uint64_t bwlG = gaddr(g_bwlo);

    // per chunk: A 2x512 + B 2x1024 = 3072 16B-chunks; 12 per thread
    auto issue_chunk = [&](int pc) {
        int och = pc >> 3, kc = pc & 7;
        int kt = kc * KC, o0 = och * 128;
        uint32_t tb = sb + (uint32_t)(pc & 1) * BUF_SZ;
        #pragma unroll
        for (int i = 0; i < 12; i++) {
            int id = tid + i * 256;
            if (id < 1024) {               // A tiles (hi then lo)
                int m = id >> 9, r = (id >> 3) & 63, c8 = id & 7;
                uint32_t so = (uint32_t)(r * 128 + ((c8 * 16) ^ ((r & 7) << 4)));
                uint64_t ga = (uint64_t)((long)r * HH + kt + c8 * 8) * 2;
                cpa16(tb + (m ? OFF_AL : OFF_AH) + so, (m ? vloG : vhiG) + ga);
            } else {                       // B tiles (hi then lo)
                int id2 = id - 1024;
                int m = id2 >> 10, r = (id2 >> 3) & 127, c8 = id2 & 7;
                uint32_t so = (uint32_t)(r * 128 + ((c8 * 16) ^ ((r & 7) << 4)));
                uint64_t gb = (uint64_t)((long)(o0 + r) * HH + kt + c8 * 8) * 2;
                cpa16(tb + (m ? OFF_BL : OFF_BH) + so, (m ? bwlG : bwhG) + gb);
            }
        }
    };

    issue_chunk(0);
    CP_COMMIT();

    float* qbF = (float*)(base + OFF_QB);
    float* w0F = (float*)(base + OFF_W0);
    float* w1F = (float*)(base + OFF_W1);
    float* w2F = (float*)(base + OFF_W2);
    float* swF = (float*)(base + OFF_SW);
    float* laF = (float*)(base + OFF_LA);
    float* scS = (float*)(base + OFF_SC);
    for (int i = tid; i < HH; i += 256) {
        qbF[i] = g_q[b * HH + i] + bias[i] + conv_b[i];
        w0F[i] = conv_w[i * 3 + 0];
        w1F[i] = conv_w[i * 3 + 1];
        w2F[i] = conv_w[i * 3 + 2];
        swF[i] = s_w[i];
    }
    if (tid < MT + 2) {
        int gt = t0 - 1 + tid;
        laF[tid] = (gt >= 0 && gt < TT) ? la[b * TT + gt] : 0.f;
    }
    if (tid < MT) scS[tid] = 0.f;

    // each warp: 32 rows (2 x m16), 32 cols (4 x n8)
    uint32_t aRow  = (uint32_t)(warp_m * 32 + (L & 15)) * 128;
    uint32_t bRow  = (uint32_t)(warp_n * 32 + (L & 7) + ((L >> 4) << 3)) * 128;
    uint32_t amask = (uint32_t)(L & 7) << 4;
    uint32_t aColK[4], bColK[4];
    #pragma unroll
    for (int kk = 0; kk < 4; kk++) {
        aColK[kk] = (uint32_t)(kk * 32 + ((L >> 4) << 4)) ^ amask;
        bColK[kk] = (uint32_t)(kk * 32 + (((L >> 3) & 1) << 4)) ^ amask;
    }

    float scp[2][2];
    scp[0][0] = scp[0][1] = scp[1][0] = scp[1][1] = 0.f;

    int pc = 0;
    for (int och = 0; och < NOCH; och++) {
        float acc[2][4][4];
        #pragma unroll
        for (int mi = 0; mi < 2; mi++)
            #pragma unroll
            for (int ni = 0; ni < 4; ni++)
                #pragma unroll
                for (int q = 0; q < 4; q++) acc[mi][ni][q] = 0.f;

        for (int kc = 0; kc < NKC; kc++, pc++) {
            bool has_next = (pc + 1 < NOCH * NKC);
            if (has_next) { issue_chunk(pc + 1); CP_COMMIT(); CP_WAIT1(); }
            else          { CP_WAIT0(); }
            __syncthreads();

            uint32_t tb = sb + (uint32_t)(pc & 1) * BUF_SZ;
            uint32_t aH = tb + OFF_AH + aRow;
            uint32_t aL = tb + OFF_AL + aRow;
            uint32_t bH = tb + OFF_BH + bRow;
            uint32_t bL = tb + OFF_BL + bRow;

            #pragma unroll
            for (int kk = 0; kk < 4; kk++) {
                uint32_t ah[2][4], al[2][4], bh[4][2], bl[4][2];
                #pragma unroll
                for (int mi = 0; mi < 2; mi++) {
                    ldsm4(ah[mi], aH + (uint32_t)(mi * 2048) + aColK[kk]);
                    ldsm4(al[mi], aL + (uint32_t)(mi * 2048) + aColK[kk]);
                }
                #pragma unroll
                for (int n2 = 0; n2 < 2; n2++) {
                    uint32_t rh[4], rl[4];
                    ldsm4(rh, bH + (uint32_t)(n2 * 2048) + bColK[kk]);
                    ldsm4(rl, bL + (uint32_t)(n2 * 2048) + bColK[kk]);
                    bh[2*n2][0] = rh[0]; bh[2*n2][1] = rh[1];
                    bh[2*n2+1][0] = rh[2]; bh[2*n2+1][1] = rh[3];
                    bl[2*n2][0] = rl[0]; bl[2*n2][1] = rl[1];
                    bl[2*n2+1][0] = rl[2]; bl[2*n2+1][1] = rl[3];
                }
                #pragma unroll
                for (int mi = 0; mi < 2; mi++)
                    #pragma unroll
                    for (int ni = 0; ni < 4; ni++) {
                        mma16816(acc[mi][ni], ah[mi], bh[ni]);
                        mma16816(acc[mi][ni], ah[mi], bl[ni]);
                        mma16816(acc[mi][ni], al[mi], bh[ni]);
                    }
            }
            __syncthreads();
        }

        int o0 = och * 128;
        #pragma unroll
        for (int mi = 0; mi < 2; mi++) {
            int r0 = warp_m * 32 + mi * 16 + (L >> 2);
            float la0 = laF[r0],     la1 = laF[r0 + 1], la2 = laF[r0 + 2];
            float lb0 = laF[r0 + 8], lb1 = laF[r0 + 9], lb2 = laF[r0 + 10];
            #pragma unroll
            for (int ni = 0; ni < 4; ni++) {
                int c0 = o0 + warp_n * 32 + ni * 8 + (L & 3) * 2;
                float2 qb = *(const float2*)(qbF + c0);
                float2 w0 = *(const float2*)(w0F + c0);
                float2 w1 = *(const float2*)(w1F + c0);
                float2 w2 = *(const float2*)(w2F + c0);
                float2 sw = *(const float2*)(swF + c0);
                float cva0 = w0.x * la0 + w1.x * la1 + w2.x * la2 + qb.x;
                float cva1 = w0.y * la0 + w1.y * la1 + w2.y * la2 + qb.y;
                float cvb0 = w0.x * lb0 + w1.x * lb1 + w2.x * lb2 + qb.x;
                float cvb1 = w0.y * lb0 + w1.y * lb1 + w2.y * lb2 + qb.y;
                scp[mi][0] += sw.x * ftanh(acc[mi][ni][0] + cva0)
                            + sw.y * ftanh(acc[mi][ni][1] + cva1);
                scp[mi][1] += sw.x * ftanh(acc[mi][ni][2] + cvb0)
                            + sw.y * ftanh(acc[mi][ni][3] + cvb1);
            }
        }
    }

    #pragma unroll
    for (int mi = 0; mi < 2; mi++)
        #pragma unroll
        for (int h = 0; h < 2; h++) {
            float v = scp[mi][h];
            v += __shfl_xor_sync(0xffffffffu, v, 1);
            v += __shfl_xor_sync(0xffffffffu, v, 2);
            if ((L & 3) == 0) {
                int r = warp_m * 32 + mi * 16 + (L >> 2) + h * 8;
                atomicAdd(&scS[r], v);
            }
        }
    __syncthreads();

    if (tid < MT) {
        float s = scS[tid];
        float p = __fdividef(1.f, 1.f + __expf(-(s + s_b[0])));
        g_p[b * TT + t0 + tid] = p;
        #pragma unroll
        for (int off = 16; off; off >>= 1)
            p += __shfl_xor_sync(0xffffffffu, p, off);
        if ((tid & 31) == 0) atomicAdd(&g_sum[b], p);
    }
}

// ---------------- context: g_ctx[b,h] += sum_t p[b,t]*value[b,t,h] ----------
__global__ void __launch_bounds__(256)
k_ctx(const float* __restrict__ value) {
    int b = blockIdx.x, ts = blockIdx.y;
    int h2 = threadIdx.x;                       // float2 column index (0..255)
    const float2* vb = (const float2*)value + ((long)b * TT + ts * 256) * 256 + h2;
    const float* pb  = g_p + b * TT + ts * 256;
    float2 a0 = {0.f, 0.f}, a1 = {0.f, 0.f}, a2 = {0.f, 0.f}, a3 = {0.f, 0.f};
    #pragma unroll 4
    for (int t = 0; t < 256; t += 4) {
        float p0 = pb[t], p1 = pb[t + 1], p2 = pb[t + 2], p3 = pb[t + 3];
        float2 v0 = vb[(long)(t + 0) * 256];
        float2 v1 = vb[(long)(t + 1) * 256];
        float2 v2 = vb[(long)(t + 2) * 256];
        float2 v3 = vb[(long)(t + 3) * 256];
        a0.x += p0 * v0.x; a0.y += p0 * v0.y;
        a1.x += p1 * v1.x; a1.y += p1 * v1.y;
        a2.x += p2 * v2.x; a2.y += p2 * v2.y;
        a3.x += p3 * v3.x; a3.y += p3 * v3.y;
    }
    float rx = (a0.x + a1.x) + (a2.x + a3.x);
    float ry = (a0.y + a1.y) + (a2.y + a3.y);
    atomicAdd(&g_ctx[b * HH + 2 * h2 + 0], rx);
    atomicAdd(&g_ctx[b * HH + 2 * h2 + 1], ry);
}

__global__ void k_fin(float* __restrict__ out) {
    int i = blockIdx.x * 256 + threadIdx.x;
    if (i < BB * HH) out[i] = g_ctx[i] / g_sum[i / HH];
    if (i < BB * TT) out[BB * HH + i] = g_p[i] / g_sum[i / TT];
}

// ---------------------------------------------------------------------------
extern "C" void kernel_launch(void* const* d_in, const int* in_sizes, int n_in,
                              void* d_out, int out_size) {
    const float* query  = (const float*)d_in[0];
    const float* value  = (const float*)d_in[1];
    const float* la     = (const float*)d_in[2];
    const float* conv_w = (const float*)d_in[3];
    const float* conv_b = (const float*)d_in[4];
    const float* q_w    = (const float*)d_in[5];
    const float* v_w    = (const float*)d_in[6];
    const float* s_w    = (const float*)d_in[7];
    const float* s_b    = (const float*)d_in[8];
    const float* bias   = (const float*)d_in[9];
    float* out = (float*)d_out;

    cudaFuncSetAttribute(k_main, cudaFuncAttributeMaxDynamicSharedMemorySize,
                         SMEM_REQ);

    k_init<<<(HH * HH + 255) / 256, 256>>>(v_w);
    k_convv<<<(BB * TT * HH / 4 + 255) / 256, 256>>>(value);
    k_qproj<<<HH, 256>>>(query, q_w);
    k_main<<<dim3(TT / MT, BB), 256, SMEM_REQ>>>(la, conv_w, conv_b,
                                                 s_w, s_b, bias);
    k_ctx<<<dim3(BB, 8), 256>>>(value);
    k_fin<<<(BB * TT + 255) / 256, 256>>>(out);
}

// round 9
// speedup vs baseline: 1.1698x; 1.0243x over previous
#include <cuda_runtime.h>
#include <cuda_bf16.h>
#include <math.h>
#include <stdint.h>

#define BB 32
#define TT 2048
#define HH 512

#define MT  64                  // t-rows per CTA
#define KC  64                  // K-chunk
#define NOCH 2                  // N chunks of 128 per CTA (half of total)
#define NC  (NOCH * (HH / KC))  // 16 chunks per CTA

// ---------------- scratch (device globals; no allocation allowed) ----------
__device__ float g_q[BB * HH];
__device__ float g_p[BB * TT];
__device__ float g_scr[BB * TT];    // raw score accumulator (pre-sigmoid)
__device__ float g_ctx[BB * HH];
__device__ float g_sum[BB];
__device__ __nv_bfloat16 g_bwhi[HH * HH];
__device__ __nv_bfloat16 g_bwlo[HH * HH];
__device__ __nv_bfloat16 g_vhi[BB * TT * HH];   // 64MB
__device__ __nv_bfloat16 g_vlo[BB * TT * HH];   // 64MB

// ---------------- SMEM layout (byte offsets from 1024-aligned base) --------
// buffer: [AH 8K][AL 8K][BH 16K][BL 16K] = 48K, 2 buffers
#define OFF_AH   0
#define OFF_AL   8192
#define OFF_BH   16384
#define OFF_BL   32768
#define BUF_SZ   49152
#define OFF_QB   98304
#define OFF_W0   100352
#define OFF_W1   102400
#define OFF_W2   104448
#define OFF_SW   106496
#define OFF_LA   108544    // 66 floats
#define SMEM_END 109056
#define SMEM_REQ (SMEM_END + 1024)   // x2 CTAs <= 227KB

// ---------------- helpers ---------------------------------------------------
__device__ __forceinline__ uint32_t smem_u32(const void* p) {
    uint32_t a;
    asm("{ .reg .u64 t; cvta.to.shared.u64 t, %1; cvt.u32.u64 %0, t; }"
        : "=r"(a) : "l"(p));
    return a;
}
__device__ __forceinline__ uint64_t gaddr(const void* p) {
    uint64_t a;
    asm("cvta.to.global.u64 %0, %1;" : "=l"(a) : "l"(p));
    return a;
}
__device__ __forceinline__ void cpa16(uint32_t d, uint64_t s) {
    asm volatile("cp.async.cg.shared.global [%0], [%1], 16;"
                 :: "r"(d), "l"(s) : "memory");
}
#define CP_COMMIT() asm volatile("cp.async.commit_group;" ::: "memory")
#define CP_WAIT0()  asm volatile("cp.async.wait_group 0;" ::: "memory")

__device__ __forceinline__ void ldsm4(uint32_t* r, uint32_t a) {
    asm volatile("ldmatrix.sync.aligned.m8n8.x4.shared.b16 {%0,%1,%2,%3}, [%4];"
                 : "=r"(r[0]), "=r"(r[1]), "=r"(r[2]), "=r"(r[3]) : "r"(a));
}
__device__ __forceinline__ void mma16816(float* d, const uint32_t* a,
                                         const uint32_t* b) {
    asm volatile(
        "mma.sync.aligned.m16n8k16.row.col.f32.bf16.bf16.f32 "
        "{%0,%1,%2,%3},{%4,%5,%6,%7},{%8,%9},{%0,%1,%2,%3};"
        : "+f"(d[0]), "+f"(d[1]), "+f"(d[2]), "+f"(d[3])
        : "r"(a[0]), "r"(a[1]), "r"(a[2]), "r"(a[3]), "r"(b[0]), "r"(b[1]));
}
__device__ __forceinline__ float ftanh(float x) {
    float y;
    asm("tanh.approx.f32 %0, %1;" : "=f"(y) : "f"(x));
    return y;
}
__device__ __forceinline__ uint32_t pkbf(float a, float b) {
    return ((uint32_t)__bfloat16_as_ushort(__float2bfloat16(b)) << 16)
         |  (uint32_t)__bfloat16_as_ushort(__float2bfloat16(a));
}

// ---------------- init: zero scratch + split v_w ----------------------------
__global__ void k_init(const float* __restrict__ v_w) {
    int i = blockIdx.x * 256 + threadIdx.x;
    if (i < BB * HH) g_ctx[i] = 0.f;
    if (i < BB)      g_sum[i] = 0.f;
    if (i < BB * TT) g_scr[i] = 0.f;
    if (i < HH * HH) {
        float x = v_w[i];
        __nv_bfloat16 h = __float2bfloat16(x);
        g_bwhi[i] = h;
        g_bwlo[i] = __float2bfloat16(x - __bfloat162float(h));
    }
}

__global__ void k_convv(const float* __restrict__ value) {
    long i4 = (long)blockIdx.x * 256 + threadIdx.x;       // 4 elems each
    float4 v = *((const float4*)value + i4);
    float hx = __bfloat162float(__float2bfloat16(v.x));
    float hy = __bfloat162float(__float2bfloat16(v.y));
    float hz = __bfloat162float(__float2bfloat16(v.z));
    float hw = __bfloat162float(__float2bfloat16(v.w));
    ((uint2*)g_vhi)[i4] = make_uint2(pkbf(v.x, v.y), pkbf(v.z, v.w));
    ((uint2*)g_vlo)[i4] = make_uint2(pkbf(v.x - hx, v.y - hy),
                                     pkbf(v.z - hz, v.w - hw));
}

// q[b,o]: one block per o; warp w covers b in [4w, 4w+4)
__global__ void __launch_bounds__(256)
k_qproj(const float* __restrict__ query, const float* __restrict__ q_w) {
    int o = blockIdx.x, lane = threadIdx.x & 31, warp = threadIdx.x >> 5;
    const float* wrow = q_w + o * HH;
    float acc0 = 0.f, acc1 = 0.f, acc2 = 0.f, acc3 = 0.f;
    int b0 = warp * 4;
    for (int k = lane; k < HH; k += 32) {
        float w = __ldg(wrow + k);
        acc0 += w * __ldg(query + (b0 + 0) * HH + k);
        acc1 += w * __ldg(query + (b0 + 1) * HH + k);
        acc2 += w * __ldg(query + (b0 + 2) * HH + k);
        acc3 += w * __ldg(query + (b0 + 3) * HH + k);
    }
    #pragma unroll
    for (int off = 16; off; off >>= 1) {
        acc0 += __shfl_xor_sync(0xffffffffu, acc0, off);
        acc1 += __shfl_xor_sync(0xffffffffu, acc1, off);
        acc2 += __shfl_xor_sync(0xffffffffu, acc2, off);
        acc3 += __shfl_xor_sync(0xffffffffu, acc3, off);
    }
    if (lane == 0) {
        g_q[(b0 + 0) * HH + o] = acc0;
        g_q[(b0 + 1) * HH + o] = acc1;
        g_q[(b0 + 2) * HH + o] = acc2;
        g_q[(b0 + 3) * HH + o] = acc3;
    }
}

// ---------------- main HMMA kernel ------------------------------------------
// CTA = (b, t-tile of 64, N-half of 256). grid (64, 32): x = t-tile*2 + nh.
__global__ void __launch_bounds__(256, 2)
k_main(const float* __restrict__ la,
       const float* __restrict__ conv_w, const float* __restrict__ conv_b,
       const float* __restrict__ s_w,    const float* __restrict__ bias)
{
    extern __shared__ char smraw[];
    uint32_t raw = smem_u32(smraw);
    uint32_t sb  = (raw + 1023) & ~1023u;
    char* base   = smraw + (sb - raw);

    int tid = threadIdx.x, L = tid & 31, wid = tid >> 5;
    int warp_m = wid >> 2, warp_n = wid & 3;      // 2 x 4
    int b  = blockIdx.y;
    int t0 = (blockIdx.x >> 1) * MT;
    int ochb = (blockIdx.x & 1) * NOCH;           // global o-chunk base (0 or 2)

    uint64_t vhiG = gaddr(g_vhi) + (uint64_t)(((long)b * TT + t0) * HH) * 2;
    uint64_t vloG = gaddr(g_vlo) + (uint64_t)(((long)b * TT + t0) * HH) * 2;
    uint64_t bwhG = gaddr(g_bwhi);
    uint64_t bwlG = gaddr(g_bwlo);

    // per chunk: A 2x512 + B 2x1024 = 3072 16B-chunks; 12 per thread
    auto issue_chunk = [&](int pc) {
        int och = ochb + (pc >> 3), kc = pc & 7;
        int kt = kc * KC, o0 = och * 128;
        uint32_t tb = sb + (uint32_t)(pc & 1) * BUF_SZ;
        #pragma unroll
        for (int i = 0; i < 12; i++) {
            int id = tid + i * 256;
            if (id < 1024) {               // A tiles (hi then lo)
                int m = id >> 9, r = (id >> 3) & 63, c8 = id & 7;
                uint32_t so = (uint32_t)(r * 128 + ((c8 * 16) ^ ((r & 7) << 4)));
                uint64_t ga = (uint64_t)((long)r * HH + kt + c8 * 8) * 2;
                cpa16(tb + (m ? OFF_AL : OFF_AH) + so, (m ? vloG : vhiG) + ga);
            } else {                       // B tiles (hi then lo)
                int id2 = id - 1024;
                int m = id2 >> 10, r = (id2 >> 3) & 127, c8 = id2 & 7;
                uint32_t so = (uint32_t)(r * 128 + ((c8 * 16) ^ ((r & 7) << 4)));
                uint64_t gb = (uint64_t)((long)(o0 + r) * HH + kt + c8 * 8) * 2;
                cpa16(tb + (m ? OFF_BL : OFF_BH) + so, (m ? bwlG : bwhG) + gb);
            }
        }
    };

    issue_chunk(0);
    CP_COMMIT();

    float* qbF = (float*)(base + OFF_QB);
    float* w0F = (float*)(base + OFF_W0);
    float* w1F = (float*)(base + OFF_W1);
    float* w2F = (float*)(base + OFF_W2);
    float* swF = (float*)(base + OFF_SW);
    float* laF = (float*)(base + OFF_LA);
    // only this CTA's 256 columns are needed; load all 512 for simplicity
    for (int i = tid; i < HH; i += 256) {
        qbF[i] = g_q[b * HH + i] + bias[i] + conv_b[i];
        w0F[i] = conv_w[i * 3 + 0];
        w1F[i] = conv_w[i * 3 + 1];
        w2F[i] = conv_w[i * 3 + 2];
        swF[i] = s_w[i];
    }
    if (tid < MT + 2) {
        int gt = t0 - 1 + tid;
        laF[tid] = (gt >= 0 && gt < TT) ? la[b * TT + gt] : 0.f;
    }

    // each warp: 32 rows (2 x m16), 32 cols (4 x n8)
    uint32_t aRow  = (uint32_t)(warp_m * 32 + (L & 15)) * 128;
    uint32_t bRow  = (uint32_t)(warp_n * 32 + (L & 7) + ((L >> 4) << 3)) * 128;
    uint32_t amask = (uint32_t)(L & 7) << 4;
    uint32_t aColK[4], bColK[4];
    #pragma unroll
    for (int kk = 0; kk < 4; kk++) {
        aColK[kk] = (uint32_t)(kk * 32 + ((L >> 4) << 4)) ^ amask;
        bColK[kk] = (uint32_t)(kk * 32 + (((L >> 3) & 1) << 4)) ^ amask;
    }

    float scp[2][2];
    scp[0][0] = scp[0][1] = scp[1][0] = scp[1][1] = 0.f;

    int pc = 0;
    for (int och = 0; och < NOCH; och++) {
        float acc[2][4][4];
        #pragma unroll
        for (int mi = 0; mi < 2; mi++)
            #pragma unroll
            for (int ni = 0; ni < 4; ni++)
                #pragma unroll
                for (int q = 0; q < 4; q++) acc[mi][ni][q] = 0.f;

        for (int kc = 0; kc < 8; kc++, pc++) {
            // one barrier per chunk: wait own groups, sync, then issue next
            CP_WAIT0();
            __syncthreads();
            if (pc + 1 < NC) { issue_chunk(pc + 1); CP_COMMIT(); }

            uint32_t tb = sb + (uint32_t)(pc & 1) * BUF_SZ;
            uint32_t aH = tb + OFF_AH + aRow;
            uint32_t aL = tb + OFF_AL + aRow;
            uint32_t bH = tb + OFF_BH + bRow;
            uint32_t bL = tb + OFF_BL + bRow;

            #pragma unroll
            for (int kk = 0; kk < 4; kk++) {
                uint32_t ah[2][4], al[2][4], bh[4][2], bl[4][2];
                #pragma unroll
                for (int mi = 0; mi < 2; mi++) {
                    ldsm4(ah[mi], aH + (uint32_t)(mi * 2048) + aColK[kk]);
                    ldsm4(al[mi], aL + (uint32_t)(mi * 2048) + aColK[kk]);
                }
                #pragma unroll
                for (int n2 = 0; n2 < 2; n2++) {
                    uint32_t rh[4], rl[4];
                    ldsm4(rh, bH + (uint32_t)(n2 * 2048) + bColK[kk]);
                    ldsm4(rl, bL + (uint32_t)(n2 * 2048) + bColK[kk]);
                    bh[2*n2][0] = rh[0]; bh[2*n2][1] = rh[1];
                    bh[2*n2+1][0] = rh[2]; bh[2*n2+1][1] = rh[3];
                    bl[2*n2][0] = rl[0]; bl[2*n2][1] = rl[1];
                    bl[2*n2+1][0] = rl[2]; bl[2*n2+1][1] = rl[3];
                }
                #pragma unroll
                for (int mi = 0; mi < 2; mi++)
                    #pragma unroll
                    for (int ni = 0; ni < 4; ni++) {
                        mma16816(acc[mi][ni], ah[mi], bh[ni]);
                        mma16816(acc[mi][ni], ah[mi], bl[ni]);
                        mma16816(acc[mi][ni], al[mi], bh[ni]);
                    }
            }
        }

        int o0 = (ochb + och) * 128;
        #pragma unroll
        for (int mi = 0; mi < 2; mi++) {
            int r0 = warp_m * 32 + mi * 16 + (L >> 2);
            float la0 = laF[r0],     la1 = laF[r0 + 1], la2 = laF[r0 + 2];
            float lb0 = laF[r0 + 8], lb1 = laF[r0 + 9], lb2 = laF[r0 + 10];
            #pragma unroll
            for (int ni = 0; ni < 4; ni++) {
                int c0 = o0 + warp_n * 32 + ni * 8 + (L & 3) * 2;
                float2 qb = *(const float2*)(qbF + c0);
                float2 w0 = *(const float2*)(w0F + c0);
                float2 w1 = *(const float2*)(w1F + c0);
                float2 w2 = *(const float2*)(w2F + c0);
                float2 sw = *(const float2*)(swF + c0);
                float cva0 = w0.x * la0 + w1.x * la1 + w2.x * la2 + qb.x;
                float cva1 = w0.y * la0 + w1.y * la1 + w2.y * la2 + qb.y;
                float cvb0 = w0.x * lb0 + w1.x * lb1 + w2.x * lb2 + qb.x;
                float cvb1 = w0.y * lb0 + w1.y * lb1 + w2.y * lb2 + qb.y;
                scp[mi][0] += sw.x * ftanh(acc[mi][ni][0] + cva0)
                            + sw.y * ftanh(acc[mi][ni][1] + cva1);
                scp[mi][1] += sw.x * ftanh(acc[mi][ni][2] + cvb0)
                            + sw.y * ftanh(acc[mi][ni][3] + cvb1);
            }
        }
    }

    // partial score for 256 columns -> global accumulator
    #pragma unroll
    for (int mi = 0; mi < 2; mi++)
        #pragma unroll
        for (int h = 0; h < 2; h++) {
            float v = scp[mi][h];
            v += __shfl_xor_sync(0xffffffffu, v, 1);
            v += __shfl_xor_sync(0xffffffffu, v, 2);
            if ((L & 3) == 0) {
                int r = warp_m * 32 + mi * 16 + (L >> 2) + h * 8;
                atomicAdd(&g_scr[b * TT + t0 + r], v);
            }
        }
}

// ---------------- sigmoid + per-batch sum -----------------------------------
__global__ void __launch_bounds__(256)
k_sig(const float* __restrict__ s_b) {
    int i = blockIdx.x * 256 + threadIdx.x;        // 65536 elems
    float p = __fdividef(1.f, 1.f + __expf(-(g_scr[i] + s_b[0])));
    g_p[i] = p;
    #pragma unroll
    for (int off = 16; off; off >>= 1)
        p += __shfl_xor_sync(0xffffffffu, p, off);
    if ((threadIdx.x & 31) == 0) atomicAdd(&g_sum[i >> 11], p);
}

// ---------------- context: g_ctx[b,h] += sum_t p[b,t]*value[b,t,h] ----------
__global__ void __launch_bounds__(256)
k_ctx(const float* __restrict__ value) {
    int b = blockIdx.x, ts = blockIdx.y;
    int h2 = threadIdx.x;                       // float2 column index (0..255)
    const float2* vb = (const float2*)value + ((long)b * TT + ts * 256) * 256 + h2;
    const float* pb  = g_p + b * TT + ts * 256;
    float2 a0 = {0.f, 0.f}, a1 = {0.f, 0.f}, a2 = {0.f, 0.f}, a3 = {0.f, 0.f};
    #pragma unroll 4
    for (int t = 0; t < 256; t += 4) {
        float p0 = pb[t], p1 = pb[t + 1], p2 = pb[t + 2], p3 = pb[t + 3];
        float2 v0 = vb[(long)(t + 0) * 256];
        float2 v1 = vb[(long)(t + 1) * 256];
        float2 v2 = vb[(long)(t + 2) * 256];
        float2 v3 = vb[(long)(t + 3) * 256];
        a0.x += p0 * v0.x; a0.y += p0 * v0.y;
        a1.x += p1 * v1.x; a1.y += p1 * v1.y;
        a2.x += p2 * v2.x; a2.y += p2 * v2.y;
        a3.x += p3 * v3.x; a3.y += p3 * v3.y;
    }
    float rx = (a0.x + a1.x) + (a2.x + a3.x);
    float ry = (a0.y + a1.y) + (a2.y + a3.y);
    atomicAdd(&g_ctx[b * HH + 2 * h2 + 0], rx);
    atomicAdd(&g_ctx[b * HH + 2 * h2 + 1], ry);
}

__global__ void k_fin(float* __restrict__ out) {
    int i = blockIdx.x * 256 + threadIdx.x;
    if (i < BB * HH) out[i] = g_ctx[i] / g_sum[i / HH];
    if (i < BB * TT) out[BB * HH + i] = g_p[i] / g_sum[i / TT];
}

// ---------------------------------------------------------------------------
extern "C" void kernel_launch(void* const* d_in, const int* in_sizes, int n_in,
                              void* d_out, int out_size) {
    const float* query  = (const float*)d_in[0];
    const float* value  = (const float*)d_in[1];
    const float* la     = (const float*)d_in[2];
    const float* conv_w = (const float*)d_in[3];
    const float* conv_b = (const float*)d_in[4];
    const float* q_w    = (const float*)d_in[5];
    const float* v_w    = (const float*)d_in[6];
    const float* s_w    = (const float*)d_in[7];
    const float* s_b    = (const float*)d_in[8];
    const float* bias   = (const float*)d_in[9];
    float* out = (float*)d_out;

    cudaFuncSetAttribute(k_main, cudaFuncAttributeMaxDynamicSharedMemorySize,
                         SMEM_REQ);

    k_init<<<(HH * HH + 255) / 256, 256>>>(v_w);
    k_convv<<<(BB * TT * HH / 4 + 255) / 256, 256>>>(value);
    k_qproj<<<HH, 256>>>(query, q_w);
    k_main<<<dim3((TT / MT) * 2, BB), 256, SMEM_REQ>>>(la, conv_w, conv_b,
                                                       s_w, bias);
    k_sig<<<BB * TT / 256, 256>>>(s_b);
    k_ctx<<<dim3(BB, 8), 256>>>(value);
    k_fin<<<(BB * TT + 255) / 256, 256>>>(out);
}